// round 8
// baseline (speedup 1.0000x reference)
#include <cuda_runtime.h>
#include <cuda_bf16.h>
#include <math.h>

#define EPS 1e-5f
#define CC 64
#define NN 8
#define HW 65536
#define P1 128
#define NB1 (HW/P1)      /* 512 */
#define P3 512
#define NB3 (HW/P3)      /* 128 */

// ---------------- scratch (__device__ globals; no allocation) ----------------
__device__ __nv_bfloat16 g_val[(size_t)2*NN*CC*HW];   // 134 MiB, [side][n][c][pix]
__device__ float g_psum[2*NN*NB1*CC];
__device__ float g_pmax[2*NN*NB1*CC];
__device__ float g_pkm[2*NN*NB1];
__device__ float g_pkz[2*NN*NB1];
__device__ float g_feap[2*NN*NB1*CC];
__device__ float g_avg[2*NN*CC];
__device__ float g_mx[2*NN*CC];
__device__ float g_gate[2*NN*CC];

__device__ __forceinline__ float fexp_(float x){ return __expf(x); }
__device__ __forceinline__ float tanhf_(float x){
    float r; asm("tanh.approx.f32 %0, %1;" : "=f"(r) : "f"(x)); return r;
}
__device__ __forceinline__ float sigmoidf_(float x){ return fmaf(0.5f, tanhf_(0.5f * x), 0.5f); }
__device__ __forceinline__ float siluf_(float x){ return x * sigmoidf_(x); }

__device__ __forceinline__ unsigned tf32_(float f){
    unsigned u; asm("cvt.rna.tf32.f32 %0, %1;" : "=r"(u) : "f"(f)); return u;
}

#define MMA_TF32(d, a, b) \
    asm volatile("mma.sync.aligned.m16n8k8.row.col.f32.tf32.tf32.f32 " \
        "{%0,%1,%2,%3}, {%4,%5,%6,%7}, {%8,%9}, {%0,%1,%2,%3};" \
        : "+f"((d)[0]), "+f"((d)[1]), "+f"((d)[2]), "+f"((d)[3]) \
        : "r"((a)[0]), "r"((a)[1]), "r"((a)[2]), "r"((a)[3]), \
          "r"((b)[0]), "r"((b)[1]))

// ---------------- kernel 1 smem layout (float offsets) ----------------
#define XSTR 136          /* x tile stride: banks 8t+g distinct */
#define WSTR 68           /* weight stride: banks 4g+t distinct */
#define VASTR 132         /* valA bf16 stage stride (halves) */
#define SM_X    0         /* 64*136 = 8704 */
#define SM_WA   8704
#define SM_WB   13056
#define SM_VA   17408     /* 64*132 halves = 4224 floats */
#define SM_KK   21632     /* 128 */
#define SM_WEA  21760     /* 128: exp(kA - mA) */
#define SM_WEB  21888     /* 128: exp(kB - mB) */
#define SM_PS   22016     /* [8][64] */
#define SM_PM   22528
#define SM_FEA  23040     /* [8][64] feaA partials */
#define SM_KWS  23552
#define SM_VSC  23616
#define SM_VSH  23680
#define SM_SCAL 23744     /* scalars / red */
#define SM1_FLOATS 23776  /* 95104 bytes */

extern __shared__ float sm1[];

__global__ __launch_bounds__(256) void k1(
    const float* __restrict__ rgb, const float* __restrict__ ir,
    const float* __restrict__ conv_w, const float* __restrict__ val_w,
    const float* __restrict__ key_w,
    const float* __restrict__ key_g, const float* __restrict__ key_b,
    const float* __restrict__ key_m, const float* __restrict__ key_v,
    const float* __restrict__ val_g, const float* __restrict__ val_b,
    const float* __restrict__ val_m, const float* __restrict__ val_v)
{
    unsigned* xs = reinterpret_cast<unsigned*>(sm1 + SM_X);
    unsigned* wa = reinterpret_cast<unsigned*>(sm1 + SM_WA);
    unsigned* wb = reinterpret_cast<unsigned*>(sm1 + SM_WB);
    __nv_bfloat16* va = reinterpret_cast<__nv_bfloat16*>(sm1 + SM_VA);
    float* kk  = sm1 + SM_KK;
    float* ps  = sm1 + SM_PS;
    float* pm  = sm1 + SM_PM;
    float* fea = sm1 + SM_FEA;
    float* kws = sm1 + SM_KWS;
    float* vsc = sm1 + SM_VSC;
    float* vsh = sm1 + SM_VSH;
    float* scal = sm1 + SM_SCAL;

    const int tid = threadIdx.x;
    const int wid = tid >> 5, lane = tid & 31;
    const int g = lane >> 2, t = lane & 3;
    const int n = blockIdx.y, blk = blockIdx.x;
    const int e0 = blk * P1;

    for (int idx = tid; idx < 4096; idx += 256) {
        int o = idx >> 6, c = idx & 63;
        wa[o * WSTR + c] = tf32_(conv_w[idx]);
        wb[o * WSTR + c] = tf32_(val_w[idx]);
    }
    if (tid < 64) {
        kws[tid] = key_w[tid];
        float sc = val_g[tid] * rsqrtf(val_v[tid] + EPS);
        vsc[tid] = sc; vsh[tid] = val_b[tid] - val_m[tid] * sc;
    }

    const int pixbase = wid * 16;
    float acc[8][4];

    for (int s = 0; s < 2; s++) {
        const float* x = (s == 0 ? rgb : ir) + (size_t)n * CC * HW;
        __syncthreads();   // xs / ps / pm free for reuse
        // ---- x tile: raw fp32 bits ----
        #pragma unroll
        for (int i = 0; i < 8; i++) {
            int idx = tid + i * 256;           // 2048 uint4
            int r = idx >> 5, c4 = idx & 31;
            uint4 u = *reinterpret_cast<const uint4*>(x + (size_t)r * HW + e0 + (c4 << 2));
            *reinterpret_cast<uint4*>(xs + r * XSTR + (c4 << 2)) = u;
        }
        __syncthreads();

        // ======== xc GEMM ========
        #pragma unroll
        for (int i = 0; i < 8; i++) { acc[i][0]=0.f; acc[i][1]=0.f; acc[i][2]=0.f; acc[i][3]=0.f; }
        #pragma unroll
        for (int ks = 0; ks < 8; ks++) {
            unsigned bfr[2][2];
            #pragma unroll
            for (int nt = 0; nt < 2; nt++) {
                int pcol = pixbase + nt * 8 + g;
                bfr[nt][0] = xs[(ks * 8 + t) * XSTR + pcol];
                bfr[nt][1] = xs[(ks * 8 + t + 4) * XSTR + pcol];
            }
            #pragma unroll
            for (int mt = 0; mt < 4; mt++) {
                int row = mt * 16 + g;
                unsigned afr[4];
                afr[0] = wa[row * WSTR + ks * 8 + t];
                afr[1] = wa[(row + 8) * WSTR + ks * 8 + t];
                afr[2] = wa[row * WSTR + ks * 8 + t + 4];
                afr[3] = wa[(row + 8) * WSTR + ks * 8 + t + 4];
                MMA_TF32(acc[mt * 2 + 0], afr, bfr[0]);
                MMA_TF32(acc[mt * 2 + 1], afr, bfr[1]);
            }
        }
        // stats epilogue
        #pragma unroll
        for (int mt = 0; mt < 4; mt++) {
            float slo = 0.f, shi = 0.f, mlo = -3.0e38f, mhi = -3.0e38f;
            #pragma unroll
            for (int nt = 0; nt < 2; nt++) {
                float c0 = acc[mt*2+nt][0], c1 = acc[mt*2+nt][1];
                float c2 = acc[mt*2+nt][2], c3 = acc[mt*2+nt][3];
                slo += c0 + c1; shi += c2 + c3;
                mlo = fmaxf(mlo, fmaxf(c0, c1));
                mhi = fmaxf(mhi, fmaxf(c2, c3));
            }
            #pragma unroll
            for (int off = 1; off < 4; off <<= 1) {
                slo += __shfl_xor_sync(0xffffffffu, slo, off);
                shi += __shfl_xor_sync(0xffffffffu, shi, off);
                mlo = fmaxf(mlo, __shfl_xor_sync(0xffffffffu, mlo, off));
                mhi = fmaxf(mhi, __shfl_xor_sync(0xffffffffu, mhi, off));
            }
            if (t == 0) {
                ps[wid * 64 + mt * 16 + g]     = slo;
                ps[wid * 64 + mt * 16 + g + 8] = shi;
                pm[wid * 64 + mt * 16 + g]     = mlo;
                pm[wid * 64 + mt * 16 + g + 8] = mhi;
            }
        }
        // key conv
        if (tid < P1) {
            const float* xf = reinterpret_cast<const float*>(xs);
            float ka = 0.f;
            #pragma unroll 8
            for (int c = 0; c < CC; c++) ka = fmaf(kws[c], xf[c * XSTR + tid], ka);
            float kscale = key_g[0] * rsqrtf(key_v[0] + EPS);
            float kbias = key_b[0] - key_m[0] * kscale;
            kk[tid] = siluf_(ka * kscale + kbias);
        }
        __syncthreads();

        if (tid < 64) {
            float sv = 0.f, mv = -3.0e38f;
            #pragma unroll
            for (int w = 0; w < 8; w++) {
                sv += ps[w * 64 + tid];
                mv = fmaxf(mv, pm[w * 64 + tid]);
            }
            size_t b = ((size_t)(s * NN + n) * NB1 + blk) * CC + tid;
            g_psum[b] = sv; g_pmax[b] = mv;
        }
        if (wid == 0) {
            float m = fmaxf(fmaxf(kk[lane], kk[lane + 32]), fmaxf(kk[lane + 64], kk[lane + 96]));
            #pragma unroll
            for (int off = 16; off; off >>= 1) m = fmaxf(m, __shfl_xor_sync(0xffffffffu, m, off));
            float z = fexp_(kk[lane] - m) + fexp_(kk[lane + 32] - m)
                    + fexp_(kk[lane + 64] - m) + fexp_(kk[lane + 96] - m);
            #pragma unroll
            for (int off = 16; off; off >>= 1) z += __shfl_xor_sync(0xffffffffu, z, off);
            if (lane == 0) {
                int b = (s * NN + n) * NB1 + blk;
                g_pkm[b] = m; g_pkz[b] = z;
                scal[0] = m;
            }
        }
        __syncthreads();
        {
            float* we = sm1 + (s == 0 ? SM_WEA : SM_WEB);
            if (tid < P1) we[tid] = fexp_(kk[tid] - scal[0]);
        }
        __syncthreads();   // wexp + stats consumed before val phase proceeds

        // ======== val GEMM ========
        #pragma unroll
        for (int i = 0; i < 8; i++) { acc[i][0]=0.f; acc[i][1]=0.f; acc[i][2]=0.f; acc[i][3]=0.f; }
        #pragma unroll
        for (int ks = 0; ks < 8; ks++) {
            unsigned bfr[2][2];
            #pragma unroll
            for (int nt = 0; nt < 2; nt++) {
                int pcol = pixbase + nt * 8 + g;
                bfr[nt][0] = xs[(ks * 8 + t) * XSTR + pcol];
                bfr[nt][1] = xs[(ks * 8 + t + 4) * XSTR + pcol];
            }
            #pragma unroll
            for (int mt = 0; mt < 4; mt++) {
                int row = mt * 16 + g;
                unsigned afr[4];
                afr[0] = wb[row * WSTR + ks * 8 + t];
                afr[1] = wb[(row + 8) * WSTR + ks * 8 + t];
                afr[2] = wb[row * WSTR + ks * 8 + t + 4];
                afr[3] = wb[(row + 8) * WSTR + ks * 8 + t + 4];
                MMA_TF32(acc[mt * 2 + 0], afr, bfr[0]);
                MMA_TF32(acc[mt * 2 + 1], afr, bfr[1]);
            }
        }
        // val epilogue: BN+SiLU; store global bf16; stage (s=0) or fea (s=1)
        __nv_bfloat16* vbase = g_val + (size_t)(s * NN + n) * CC * HW;
        const float* weA = sm1 + SM_WEA;
        float feal[8];
        #pragma unroll
        for (int i = 0; i < 8; i++) feal[i] = 0.f;
        #pragma unroll
        for (int mt = 0; mt < 4; mt++) {
            int o = mt * 16 + g, o2 = o + 8;
            float sc = vsc[o],  sh = vsh[o];
            float sc2 = vsc[o2], sh2 = vsh[o2];
            #pragma unroll
            for (int nt = 0; nt < 2; nt++) {
                int p = pixbase + nt * 8 + 2 * t;
                float v0 = siluf_(fmaf(acc[mt*2+nt][0], sc, sh));
                float v1 = siluf_(fmaf(acc[mt*2+nt][1], sc, sh));
                float v2 = siluf_(fmaf(acc[mt*2+nt][2], sc2, sh2));
                float v3 = siluf_(fmaf(acc[mt*2+nt][3], sc2, sh2));
                __nv_bfloat162 lo = __float22bfloat162_rn(make_float2(v0, v1));
                __nv_bfloat162 hi = __float22bfloat162_rn(make_float2(v2, v3));
                *reinterpret_cast<unsigned*>(&vbase[(size_t)o  * HW + e0 + p]) = *reinterpret_cast<unsigned*>(&lo);
                *reinterpret_cast<unsigned*>(&vbase[(size_t)o2 * HW + e0 + p]) = *reinterpret_cast<unsigned*>(&hi);
                if (s == 0) {
                    *reinterpret_cast<unsigned*>(&va[o  * VASTR + p]) = *reinterpret_cast<unsigned*>(&lo);
                    *reinterpret_cast<unsigned*>(&va[o2 * VASTR + p]) = *reinterpret_cast<unsigned*>(&hi);
                } else {
                    float w0 = weA[p], w1 = weA[p + 1];
                    feal[mt*2+0] = fmaf(v0, w0, fmaf(v1, w1, feal[mt*2+0]));
                    feal[mt*2+1] = fmaf(v2, w0, fmaf(v3, w1, feal[mt*2+1]));
                }
            }
        }
        if (s == 1) {
            // reduce feaA over t lanes, stage per warp
            #pragma unroll
            for (int mt = 0; mt < 4; mt++) {
                float flo = feal[mt*2], fhi = feal[mt*2+1];
                #pragma unroll
                for (int off = 1; off < 4; off <<= 1) {
                    flo += __shfl_xor_sync(0xffffffffu, flo, off);
                    fhi += __shfl_xor_sync(0xffffffffu, fhi, off);
                }
                if (t == 0) {
                    fea[wid * 64 + mt * 16 + g]     = flo;
                    fea[wid * 64 + mt * 16 + g + 8] = fhi;
                }
            }
            __syncthreads();
            // fea_B: per warp 8 channels of valA (smem) x wexpB
            const float* weB = sm1 + SM_WEB;
            #pragma unroll
            for (int j = 0; j < 8; j++) {
                int c = wid * 8 + j;
                float a = 0.f;
                #pragma unroll
                for (int i = 0; i < 4; i++) {
                    int px = lane + 32 * i;
                    a = fmaf(__bfloat162float(va[c * VASTR + px]), weB[px], a);
                }
                #pragma unroll
                for (int off = 16; off; off >>= 1) a += __shfl_xor_sync(0xffffffffu, a, off);
                if (lane == 0)
                    g_feap[((size_t)(NN + n) * NB1 + blk) * CC + c] = a;
            }
            if (tid < 64) {
                float f = 0.f;
                #pragma unroll
                for (int w = 0; w < 8; w++) f += fea[w * 64 + tid];
                g_feap[((size_t)n * NB1 + blk) * CC + tid] = f;
            }
        }
    }
}

// ---------------- kernel 2f: M/Z + fea + softmaxes + gate ----------------
__global__ __launch_bounds__(256) void k2f(
    const float* __restrict__ conv_b, const float* __restrict__ convb_w,
    const float* __restrict__ ln_g, const float* __restrict__ ln_b)
{
    const int n = blockIdx.x, s = blockIdx.y;
    const int tid = threadIdx.x, c = tid & 63, r = tid >> 6;
    const int wid = tid >> 5, lane = tid & 31;
    const int sn = s * NN + n;
    __shared__ float t4[4][64], m4[4][64], f4[4][64];
    __shared__ float mean_s[64], mx_s[64], feas[64], gv[64];
    __shared__ float red[8];
    __shared__ float MZ[2];
    __shared__ float mu_s, var_s;

    const size_t kb = (size_t)sn * NB1;
    // key M
    float m = fmaxf(g_pkm[kb + tid], g_pkm[kb + tid + 256]);
    #pragma unroll
    for (int off = 16; off; off >>= 1) m = fmaxf(m, __shfl_xor_sync(0xffffffffu, m, off));
    if (lane == 0) red[wid] = m;
    __syncthreads();
    if (tid == 0) {
        float mm = red[0];
        #pragma unroll
        for (int i = 1; i < 8; i++) mm = fmaxf(mm, red[i]);
        MZ[0] = mm;
    }
    __syncthreads();
    const float M = MZ[0];
    // key Z
    float z = g_pkz[kb + tid] * fexp_(g_pkm[kb + tid] - M)
            + g_pkz[kb + tid + 256] * fexp_(g_pkm[kb + tid + 256] - M);
    #pragma unroll
    for (int off = 16; off; off >>= 1) z += __shfl_xor_sync(0xffffffffu, z, off);
    if (lane == 0) red[wid] = z;
    __syncthreads();
    if (tid == 0) {
        float zz = 0.f;
        #pragma unroll
        for (int i = 0; i < 8; i++) zz += red[i];
        MZ[1] = zz;
    }
    __syncthreads();
    const float invZ = __fdividef(1.f, MZ[1]);

    // combined reduction over 512 blocks: psum, pmax, fea
    float sv = 0.f, mv = -3.0e38f, fv = 0.f;
    for (int b = r; b < NB1; b += 4) {
        size_t ib = (kb + b) * CC + c;
        sv += g_psum[ib];
        mv = fmaxf(mv, g_pmax[ib]);
        fv = fmaf(g_feap[ib], fexp_(g_pkm[kb + b] - M), fv);
    }
    t4[r][c] = sv; m4[r][c] = mv; f4[r][c] = fv;
    __syncthreads();
    if (r == 0) {
        float sum = t4[0][c] + t4[1][c] + t4[2][c] + t4[3][c];
        float mx  = fmaxf(fmaxf(m4[0][c], m4[1][c]), fmaxf(m4[2][c], m4[3][c]));
        mean_s[c] = sum * (1.f / HW) + conv_b[c];
        mx_s[c]   = mx + conv_b[c];
        feas[c]   = (f4[0][c] + f4[1][c] + f4[2][c] + f4[3][c]) * invZ;
    }
    __syncthreads();

    if (tid < 32) {
        float a0 = mean_s[tid], a1 = mean_s[tid + 32];
        float m1 = fmaxf(a0, a1);
        #pragma unroll
        for (int off = 16; off; off >>= 1) m1 = fmaxf(m1, __shfl_xor_sync(0xffffffffu, m1, off));
        float e0_ = fexp_(a0 - m1), e1_ = fexp_(a1 - m1);
        float zz = e0_ + e1_;
        #pragma unroll
        for (int off = 16; off; off >>= 1) zz += __shfl_xor_sync(0xffffffffu, zz, off);
        float inv = __fdividef(1.f, zz);
        g_avg[sn * CC + tid]      = e0_ * inv;
        g_avg[sn * CC + tid + 32] = e1_ * inv;

        float b0 = mx_s[tid], b1 = mx_s[tid + 32];
        float m2 = fmaxf(b0, b1);
        #pragma unroll
        for (int off = 16; off; off >>= 1) m2 = fmaxf(m2, __shfl_xor_sync(0xffffffffu, m2, off));
        float f0 = fexp_(b0 - m2), f1 = fexp_(b1 - m2);
        float z2 = f0 + f1;
        #pragma unroll
        for (int off = 16; off; off >>= 1) z2 += __shfl_xor_sync(0xffffffffu, z2, off);
        float inv2 = __fdividef(1.f, z2);
        g_mx[sn * CC + tid]      = f0 * inv2;
        g_mx[sn * CC + tid + 32] = f1 * inv2;
    }

    if (tid < 64) {
        float gacc = 0.f;
        #pragma unroll 8
        for (int j = 0; j < CC; j++) gacc = fmaf(convb_w[c * CC + j], feas[j], gacc);
        gv[c] = gacc;
    }
    __syncthreads();
    if (tid < 32) {
        float a = gv[tid] + gv[tid + 32];
        float b2 = gv[tid] * gv[tid] + gv[tid + 32] * gv[tid + 32];
        #pragma unroll
        for (int off = 16; off; off >>= 1) {
            a  += __shfl_xor_sync(0xffffffffu, a, off);
            b2 += __shfl_xor_sync(0xffffffffu, b2, off);
        }
        if (tid == 0) {
            float mu = a * (1.f / CC);
            mu_s = mu;
            var_s = b2 * (1.f / CC) - mu * mu;
        }
    }
    __syncthreads();
    if (tid < 64) {
        float d = gv[c] - mu_s;
        float zz = d * rsqrtf(var_s + EPS) * ln_g[c] + ln_b[c];
        g_gate[sn * CC + c] = sigmoidf_(zz);
    }
}

// ---------------- kernel 3: output = gate * half + me ----------------
__global__ __launch_bounds__(256) void k3(
    const float* __restrict__ rgb, const float* __restrict__ ir, float* __restrict__ out,
    const float* __restrict__ half_w,
    const float* __restrict__ half_g, const float* __restrict__ half_b,
    const float* __restrict__ half_m, const float* __restrict__ half_v)
{
    const int s = blockIdx.z, n = blockIdx.y;
    const int e0 = blockIdx.x * P3;
    const int tid = threadIdx.x;
    __shared__ float avs[64];
    __shared__ float mxs[64];
    __shared__ float gts[64];
    if (tid < 64) {
        int i = (s * NN + n) * CC + tid;
        avs[tid] = g_avg[i]; mxs[tid] = g_mx[i]; gts[tid] = g_gate[i];
    }
    __syncthreads();

    const unsigned* vp = reinterpret_cast<const unsigned*>(
        g_val + (size_t)((1 - s) * NN + n) * CC * HW);
    const size_t pix2 = (size_t)(e0 >> 1) + tid;
    float aA0 = 0.f, aA1 = 0.f, aM0 = 0.f, aM1 = 0.f;
    #pragma unroll 8
    for (int c = 0; c < CC; c++) {
        unsigned u = vp[(size_t)c * (HW / 2) + pix2];
        float2 v = __bfloat1622float2(*reinterpret_cast<__nv_bfloat162*>(&u));
        aA0 = fmaf(v.x, avs[c], aA0); aA1 = fmaf(v.y, avs[c], aA1);
        aM0 = fmaf(v.x, mxs[c], aM0); aM1 = fmaf(v.y, mxs[c], aM1);
    }
    float hs = half_g[0] * rsqrtf(half_v[0] + EPS);
    float hb = half_b[0] - half_m[0] * hs;
    float hlf0 = siluf_((half_w[0] * aA0 + half_w[1] * aM0) * hs + hb);
    float hlf1 = siluf_((half_w[0] * aA1 + half_w[1] * aM1) * hs + hb);

    const float* xme = (s == 0 ? rgb : ir) + (size_t)n * CC * HW;
    float* op = out + (size_t)(s * NN + n) * CC * HW;
    const int p0 = e0 + 2 * tid;
    #pragma unroll 8
    for (int c = 0; c < CC; c++) {
        size_t idx = (size_t)c * HW + p0;
        float2 xv = *reinterpret_cast<const float2*>(xme + idx);
        float2 ov;
        ov.x = fmaf(gts[c], hlf0, xv.x);
        ov.y = fmaf(gts[c], hlf1, xv.y);
        *reinterpret_cast<float2*>(op + idx) = ov;
    }
}

// ---------------- launch ----------------
extern "C" void kernel_launch(void* const* d_in, const int* in_sizes, int n_in,
                              void* d_out, int out_size)
{
    const float* rgb     = (const float*)d_in[0];
    const float* ir      = (const float*)d_in[1];
    const float* conv_w  = (const float*)d_in[2];
    const float* conv_b  = (const float*)d_in[3];
    const float* key_w   = (const float*)d_in[4];
    const float* key_g   = (const float*)d_in[5];
    const float* key_b   = (const float*)d_in[6];
    const float* key_m   = (const float*)d_in[7];
    const float* key_v   = (const float*)d_in[8];
    const float* val_w   = (const float*)d_in[9];
    const float* val_g   = (const float*)d_in[10];
    const float* val_b   = (const float*)d_in[11];
    const float* val_m   = (const float*)d_in[12];
    const float* val_v   = (const float*)d_in[13];
    const float* convb_w = (const float*)d_in[14];
    const float* half_w  = (const float*)d_in[15];
    const float* half_g  = (const float*)d_in[16];
    const float* half_b  = (const float*)d_in[17];
    const float* half_m  = (const float*)d_in[18];
    const float* half_v  = (const float*)d_in[19];
    const float* ln_g    = (const float*)d_in[20];
    const float* ln_b    = (const float*)d_in[21];
    float* out = (float*)d_out;

    const size_t smem1 = SM1_FLOATS * sizeof(float);   // 95104 B
    cudaFuncSetAttribute(k1, cudaFuncAttributeMaxDynamicSharedMemorySize, (int)smem1);

    k1<<<dim3(NB1, NN), 256, smem1>>>(rgb, ir, conv_w, val_w, key_w,
                                      key_g, key_b, key_m, key_v,
                                      val_g, val_b, val_m, val_v);
    k2f<<<dim3(NN, 2), 256>>>(conv_b, convb_w, ln_g, ln_b);
    k3<<<dim3(NB3, NN, 2), 256>>>(rgb, ir, out, half_w, half_g, half_b, half_m, half_v);
}